// round 5
// baseline (speedup 1.0000x reference)
#include <cuda_runtime.h>
#include <cuda_bf16.h>

// InverseLeakySoftplus: solve a*x + (1-a)*softplus(x) = y, a = 0.1+0.4*sigmoid(raw_alpha).
//
// R4 finding: with table-init + 1 Halley, MUFU (3/elem) + LDS was still ~24us
// above the ~34us HBM floor. R5: eliminate ALL transcendentals from the main
// path via cubic Hermite interpolation of the inverse:
//   knots y_k = -16 + k*0.05, store x(y_k) and m_k = h/f'(x(y_k)).
//   Hermite err = h^4/384 * max|x''''| ~= 1.6e-8 * 200 ~= 3e-6 abs.
// Outside [-16,16] (inputs are N(0,3); 5.3 sigma): x=y (err ~1e-7) / x=y/a (exact).
// Main kernel: 1 LDS.128 + ~12 FMA/ALU per element -> memory-bound.

#define NSEG  640
#define YMINF (-16.0f)
#define H_F   0.05f
#define INVH  20.0f
#define TOFF  320.0f          // -YMIN/h
#define TPB   256
#define IPT   4               // float4 per thread

__device__ float4 g_tab4[NSEG];   // {x_k, m_k, x_{k+1}, m_{k+1}}
__device__ float  g_inva;

// ---------- table builder: 1282 Newton solves total, ~us ----------
__device__ __forceinline__ void solve_knot(float y, float a, float oma, float inva,
                                           float* x_out, float* m_out)
{
    float x = (y > 0.0f) ? y : y * inva;
#pragma unroll
    for (int it = 0; it < 10; ++it) {            // to fp32 fixed point
        float e  = __expf(-fabsf(x));
        float op = 1.0f + e;
        float sp = __logf(op) + fmaxf(x, 0.0f);
        float fx = fmaf(a, x, oma * sp);
        float num = (x >= 0.0f) ? fmaf(a, e, 1.0f) : (a + e);
        x -= __fdividef((fx - y) * op, num);
    }
    float e  = __expf(-fabsf(x));
    float op = 1.0f + e;
    float num = (x >= 0.0f) ? fmaf(a, e, 1.0f) : (a + e);
    *x_out = x;
    *m_out = H_F * op * __fdividef(1.0f, num);   // h / f'(x)
}

__global__ void build_table(const float* __restrict__ raw_alpha)
{
    int k = blockIdx.x * blockDim.x + threadIdx.x;
    float r    = __ldg(raw_alpha);
    float sig  = __fdividef(1.0f, 1.0f + __expf(-r));
    float a    = fmaf(0.4f, sig, 0.1f);
    float oma  = 1.0f - a;
    float inva = __fdividef(1.0f, a);
    if (k == 0) g_inva = inva;
    if (k < NSEG) {
        float x0, m0, x1, m1;
        solve_knot(YMINF + (float)k * H_F,       a, oma, inva, &x0, &m0);
        solve_knot(YMINF + (float)(k + 1) * H_F, a, oma, inva, &x1, &m1);
        g_tab4[k] = make_float4(x0, m0, x1, m1);
    }
}

// ---------- main: cubic Hermite, zero MUFU ----------
__device__ __forceinline__ float hermite_solve(float y, float inva,
                                               const float4* __restrict__ s_tab)
{
    float t = fmaf(y, INVH, TOFF);
    t = fminf(fmaxf(t, 0.0f), (float)NSEG - 0.001f);
    int   k  = (int)t;
    float fr = t - (float)k;
    float4 p = s_tab[k];
    float dx = p.z - p.x;
    float c3 = (p.y + p.w) - (dx + dx);          // m0+m1-2*delta
    float c2 = dx - p.y - c3;                    // 3*delta-2*m0-m1
    float x  = fmaf(fr, fmaf(fr, fmaf(fr, c3, c2), p.y), p.x);
    x = (y >=  16.0f) ? y        : x;
    x = (y <= -16.0f) ? y * inva : x;
    return x;
}

__global__ void inv_lsp_main(const float4* __restrict__ in,
                             float4* __restrict__ out, int n4)
{
    __shared__ float4 s_tab[NSEG];
    for (int j = threadIdx.x; j < NSEG; j += TPB) s_tab[j] = g_tab4[j];
    float inva = g_inva;
    __syncthreads();

    int base = blockIdx.x * (TPB * IPT) + threadIdx.x;
    float4 v[IPT];
    int    ok[IPT];
#pragma unroll
    for (int j = 0; j < IPT; ++j) {              // front-batch loads (MLP)
        int i = base + j * TPB;
        ok[j] = (i < n4);
        if (ok[j]) v[j] = in[i];
    }
#pragma unroll
    for (int j = 0; j < IPT; ++j) {
        if (ok[j]) {
            float4 rr;
            rr.x = hermite_solve(v[j].x, inva, s_tab);
            rr.y = hermite_solve(v[j].y, inva, s_tab);
            rr.z = hermite_solve(v[j].z, inva, s_tab);
            rr.w = hermite_solve(v[j].w, inva, s_tab);
            out[base + j * TPB] = rr;
        }
    }
}

// ---------- scalar tail (safety; n % 4 == 0 here) ----------
__global__ void inv_lsp_scalar_tail(const float* __restrict__ in,
                                    float* __restrict__ out,
                                    int start, int n)
{
    int i = start + blockIdx.x * blockDim.x + threadIdx.x;
    if (i >= n) return;
    float inva = g_inva;
    float a    = __fdividef(1.0f, inva);
    float oma  = 1.0f - a;
    float y = in[i];
    float x = (y > 0.0f) ? y : y * inva;
#pragma unroll
    for (int it = 0; it < 8; ++it) {
        float e  = __expf(-fabsf(x));
        float op = 1.0f + e;
        float sp = __logf(op) + fmaxf(x, 0.0f);
        float fx = fmaf(a, x, oma * sp);
        float num = (x >= 0.0f) ? fmaf(a, e, 1.0f) : (a + e);
        x -= __fdividef((fx - y) * op, num);
    }
    out[i] = x;
}

extern "C" void kernel_launch(void* const* d_in, const int* in_sizes, int n_in,
                              void* d_out, int out_size)
{
    const float* in        = (const float*)d_in[0];
    const float* raw_alpha = (const float*)d_in[1];
    float* out             = (float*)d_out;
    int n = in_sizes[0];

    build_table<<<(NSEG + 127) / 128, 128>>>(raw_alpha);

    int n4 = n / 4;
    if (n4 > 0) {
        int per_block = TPB * IPT;
        int blocks = (n4 + per_block - 1) / per_block;
        inv_lsp_main<<<blocks, TPB>>>((const float4*)in, (float4*)out, n4);
    }
    int rem = n - n4 * 4;
    if (rem > 0) {
        inv_lsp_scalar_tail<<<1, 256>>>(in, out, n4 * 4, n);
    }
}